// round 1
// baseline (speedup 1.0000x reference)
#include <cuda_runtime.h>
#include <cuda_bf16.h>

// Shapes (fixed by the problem)
#define BATCH 4
#define SEQ 2048
#define DMODEL 1024
#define NHEADS 16
#define HDIM 64
#define MROWS (BATCH * SEQ)      // 8192

// Scratch (device globals: allocation is forbidden)
__device__ float g_q[BATCH * NHEADS * SEQ * HDIM];    // [B,H,S,Dh]
__device__ float g_k[BATCH * NHEADS * SEQ * HDIM];
__device__ float g_v[BATCH * NHEADS * SEQ * HDIM];
__device__ float g_ao[BATCH * SEQ * DMODEL];          // [B,S,D]

// ---------------------------------------------------------------------------
// GEMM: C = A[M,K] * B[N,K]^T   (both K-contiguous, "NT")
// M=8192, N=1024, K=1024. Block tile 128x128x16, 256 threads, 8x8 per thread.
// mode 0: scatter output to [B,H,S,Dh] head layout (QKV projections)
// mode 1: plain row-major [M,N] (O projection)
// ---------------------------------------------------------------------------
__global__ __launch_bounds__(256) void gemm_nt_kernel(
    const float* __restrict__ A, const float* __restrict__ B,
    float* __restrict__ C, int mode)
{
    __shared__ float As[16][132];   // padded to break transpose-store conflicts
    __shared__ float Bs[16][132];

    const int tid = threadIdx.x;
    const int tx = tid & 15;        // 0..15 -> n
    const int ty = tid >> 4;        // 0..15 -> m
    const int bm = blockIdx.y << 7;
    const int bn = blockIdx.x << 7;

    const int lr = tid >> 2;        // 0..63  load row
    const int lc = (tid & 3) << 2;  // 0,4,8,12 load col (float4)

    const float* Ab = A + (bm + lr) * DMODEL + lc;
    const float* Bb = B + (bn + lr) * DMODEL + lc;

    float acc[8][8];
#pragma unroll
    for (int i = 0; i < 8; i++)
#pragma unroll
        for (int j = 0; j < 8; j++) acc[i][j] = 0.0f;

    for (int k0 = 0; k0 < DMODEL; k0 += 16) {
        float4 a0 = *(const float4*)(Ab + k0);
        float4 a1 = *(const float4*)(Ab + 64 * DMODEL + k0);
        float4 b0 = *(const float4*)(Bb + k0);
        float4 b1 = *(const float4*)(Bb + 64 * DMODEL + k0);
        __syncthreads();
        As[lc + 0][lr] = a0.x; As[lc + 1][lr] = a0.y;
        As[lc + 2][lr] = a0.z; As[lc + 3][lr] = a0.w;
        As[lc + 0][lr + 64] = a1.x; As[lc + 1][lr + 64] = a1.y;
        As[lc + 2][lr + 64] = a1.z; As[lc + 3][lr + 64] = a1.w;
        Bs[lc + 0][lr] = b0.x; Bs[lc + 1][lr] = b0.y;
        Bs[lc + 2][lr] = b0.z; Bs[lc + 3][lr] = b0.w;
        Bs[lc + 0][lr + 64] = b1.x; Bs[lc + 1][lr + 64] = b1.y;
        Bs[lc + 2][lr + 64] = b1.z; Bs[lc + 3][lr + 64] = b1.w;
        __syncthreads();
#pragma unroll
        for (int kk = 0; kk < 16; kk++) {
            float4 aA = *(const float4*)&As[kk][ty * 8];
            float4 aB = *(const float4*)&As[kk][ty * 8 + 4];
            float4 bA = *(const float4*)&Bs[kk][tx * 8];
            float4 bB = *(const float4*)&Bs[kk][tx * 8 + 4];
            float ar[8] = {aA.x, aA.y, aA.z, aA.w, aB.x, aB.y, aB.z, aB.w};
            float br[8] = {bA.x, bA.y, bA.z, bA.w, bB.x, bB.y, bB.z, bB.w};
#pragma unroll
            for (int i = 0; i < 8; i++)
#pragma unroll
                for (int j = 0; j < 8; j++)
                    acc[i][j] += ar[i] * br[j];
        }
    }

#pragma unroll
    for (int i = 0; i < 8; i++) {
        const int m = bm + ty * 8 + i;
        const int b = m >> 11;          // /SEQ
        const int s = m & (SEQ - 1);
#pragma unroll
        for (int jv = 0; jv < 8; jv += 4) {
            const int n = bn + tx * 8 + jv;
            float4 v = make_float4(acc[i][jv], acc[i][jv + 1],
                                   acc[i][jv + 2], acc[i][jv + 3]);
            if (mode == 0) {
                const int h = n >> 6;
                const int dh = n & 63;
                *(float4*)&C[((b * NHEADS + h) * SEQ + s) * HDIM + dh] = v;
            } else {
                *(float4*)&C[m * DMODEL + n] = v;
            }
        }
    }
}

// ---------------------------------------------------------------------------
// Flash attention (fp32, causal). One block = one (b,h) x 64-query tile.
// 256 threads: thread -> (q = tid>>2, sub = tid&3).
// Phase1: scores for k = sub + 4*jj (interleaved -> conflict-free Ks reads).
// Phase2: PV with dh = 16*j4 + 4*sub (+lane) (conflict-free Vs reads).
// ---------------------------------------------------------------------------
#define QS_STRIDE 68
#define KS_STRIDE 68
#define PS_STRIDE 65
#define ATT_SMEM_FLOATS (64 * QS_STRIDE + 64 * KS_STRIDE + 64 * 64 + 64 * PS_STRIDE)

__global__ __launch_bounds__(256) void attn_kernel(
    const float* __restrict__ Q, const float* __restrict__ K,
    const float* __restrict__ V, float* __restrict__ O)
{
    extern __shared__ float sm[];
    float* Qs = sm;                       // [64][68]
    float* Ks = Qs + 64 * QS_STRIDE;      // [64][68]
    float* Vs = Ks + 64 * KS_STRIDE;      // [64][64]
    float* Ps = Vs + 64 * 64;             // [64][65]

    const int tid = threadIdx.x;
    const int bh = blockIdx.y;            // b*16 + h
    const int q0 = blockIdx.x << 6;
    const float* Qb = Q + bh * (SEQ * HDIM);
    const float* Kb = K + bh * (SEQ * HDIM);
    const float* Vb = V + bh * (SEQ * HDIM);

    const int lr = tid >> 2;              // 0..63
    const int sub = tid & 3;
    const int lc = sub << 4;              // 0,16,32,48

    // Q tile -> smem
#pragma unroll
    for (int c = 0; c < 16; c += 4)
        *(float4*)&Qs[lr * QS_STRIDE + lc + c] =
            *(const float4*)&Qb[(q0 + lr) * HDIM + lc + c];

    const int q = lr;
    float acc[16];
#pragma unroll
    for (int i = 0; i < 16; i++) acc[i] = 0.0f;
    float m_run = -1e30f, l_run = 0.0f;

    const int ntiles = blockIdx.x + 1;    // causal: k-tiles 0..qtile
    for (int t = 0; t < ntiles; t++) {
        const int k0 = t << 6;
        __syncthreads();   // prev iter done with Ks/Vs/Ps; Qs visible (t==0)
#pragma unroll
        for (int c = 0; c < 16; c += 4) {
            *(float4*)&Ks[lr * KS_STRIDE + lc + c] =
                *(const float4*)&Kb[(k0 + lr) * HDIM + lc + c];
            *(float4*)&Vs[lr * 64 + lc + c] =
                *(const float4*)&Vb[(k0 + lr) * HDIM + lc + c];
        }
        __syncthreads();

        // ---- scores: 16 k per thread, 2 k at a time (reuse Q loads) ----
        float sc[16];
#pragma unroll
        for (int jj = 0; jj < 16; jj += 2) {
            const int ka = sub + 4 * jj;
            const int kb = ka + 4;
            float sa = 0.0f, sb = 0.0f;
#pragma unroll
            for (int d = 0; d < HDIM; d += 4) {
                float4 qv  = *(const float4*)&Qs[q * QS_STRIDE + d];
                float4 kva = *(const float4*)&Ks[ka * KS_STRIDE + d];
                float4 kvb = *(const float4*)&Ks[kb * KS_STRIDE + d];
                sa += qv.x * kva.x + qv.y * kva.y + qv.z * kva.z + qv.w * kva.w;
                sb += qv.x * kvb.x + qv.y * kvb.y + qv.z * kvb.z + qv.w * kvb.w;
            }
            sc[jj] = sa; sc[jj + 1] = sb;
        }

        // causal mask + scale (1/sqrt(64) = 0.125)
        const int qg = q0 + q;
#pragma unroll
        for (int jj = 0; jj < 16; jj++) {
            const int kg = k0 + sub + 4 * jj;
            sc[jj] = (kg <= qg) ? sc[jj] * 0.125f : -1e30f;
        }

        // online softmax (group of 4 lanes shares a q-row)
        float tm = sc[0];
#pragma unroll
        for (int jj = 1; jj < 16; jj++) tm = fmaxf(tm, sc[jj]);
        tm = fmaxf(tm, __shfl_xor_sync(0xffffffffu, tm, 1));
        tm = fmaxf(tm, __shfl_xor_sync(0xffffffffu, tm, 2));
        const float m_new = fmaxf(m_run, tm);
        const float alpha = __expf(m_run - m_new);
        float lsum = 0.0f;
#pragma unroll
        for (int jj = 0; jj < 16; jj++) {
            const float p = __expf(sc[jj] - m_new);
            lsum += p;
            Ps[q * PS_STRIDE + sub + 4 * jj] = p;
        }
        lsum += __shfl_xor_sync(0xffffffffu, lsum, 1);
        lsum += __shfl_xor_sync(0xffffffffu, lsum, 2);
        l_run = l_run * alpha + lsum;
        m_run = m_new;
#pragma unroll
        for (int i = 0; i < 16; i++) acc[i] *= alpha;
        __syncthreads();

        // ---- PV: thread accumulates dh = 16*j4 + 4*sub + (0..3) ----
#pragma unroll 8
        for (int k = 0; k < 64; k++) {
            const float pk = Ps[q * PS_STRIDE + k];
#pragma unroll
            for (int j4 = 0; j4 < 4; j4++) {
                float4 vv = *(const float4*)&Vs[k * 64 + (sub << 2) + (j4 << 4)];
                acc[j4 * 4 + 0] += pk * vv.x;
                acc[j4 * 4 + 1] += pk * vv.y;
                acc[j4 * 4 + 2] += pk * vv.z;
                acc[j4 * 4 + 3] += pk * vv.w;
            }
        }
    }

    const float rinv = 1.0f / l_run;
    const int b = bh >> 4, h = bh & 15;
    float* Ob = O + (b * SEQ + q0 + q) * DMODEL + h * HDIM;
#pragma unroll
    for (int j4 = 0; j4 < 4; j4++) {
        float4 v = make_float4(acc[j4 * 4 + 0] * rinv, acc[j4 * 4 + 1] * rinv,
                               acc[j4 * 4 + 2] * rinv, acc[j4 * 4 + 3] * rinv);
        *(float4*)&Ob[(sub << 2) + (j4 << 4)] = v;
    }
}

// ---------------------------------------------------------------------------
extern "C" void kernel_launch(void* const* d_in, const int* in_sizes, int n_in,
                              void* d_out, int out_size)
{
    const float* x  = (const float*)d_in[0];
    const float* wq = (const float*)d_in[1];
    const float* wk = (const float*)d_in[2];
    const float* wv = (const float*)d_in[3];
    const float* wo = (const float*)d_in[4];
    float* out = (float*)d_out;

    float *pq, *pk, *pv, *pao;
    cudaGetSymbolAddress((void**)&pq,  g_q);
    cudaGetSymbolAddress((void**)&pk,  g_k);
    cudaGetSymbolAddress((void**)&pv,  g_v);
    cudaGetSymbolAddress((void**)&pao, g_ao);

    const dim3 ggrid(DMODEL / 128, MROWS / 128);   // (8, 64)
    gemm_nt_kernel<<<ggrid, 256>>>(x, wq, pq, 0);
    gemm_nt_kernel<<<ggrid, 256>>>(x, wk, pk, 0);
    gemm_nt_kernel<<<ggrid, 256>>>(x, wv, pv, 0);

    cudaFuncSetAttribute(attn_kernel, cudaFuncAttributeMaxDynamicSharedMemorySize,
                         ATT_SMEM_FLOATS * (int)sizeof(float));
    const dim3 agrid(SEQ / 64, BATCH * NHEADS);    // (32, 64)
    attn_kernel<<<agrid, 256, ATT_SMEM_FLOATS * sizeof(float)>>>(pq, pk, pv, pao);

    gemm_nt_kernel<<<ggrid, 256>>>(pao, wo, out, 1);
}

// round 2
// speedup vs baseline: 1.1748x; 1.1748x over previous
#include <cuda_runtime.h>
#include <cuda_bf16.h>
#include <cstdint>

// Shapes (fixed by the problem)
#define BATCH 4
#define SEQ 2048
#define DMODEL 1024
#define NHEADS 16
#define HDIM 64
#define MROWS (BATCH * SEQ)      // 8192

// Scratch (device globals: allocation is forbidden)
__device__ float g_q[BATCH * NHEADS * SEQ * HDIM];    // [B,H,S,Dh]
__device__ float g_k[BATCH * NHEADS * SEQ * HDIM];
__device__ float g_v[BATCH * NHEADS * SEQ * HDIM];
__device__ float g_ao[BATCH * SEQ * DMODEL];          // [B,S,D]

// ---------------------------------------------------------------------------
// tf32 tensor-core GEMM: C = A[M,K] * B[N,K]^T  ("NT", both K-contiguous)
// M=8192, N=1024, K=1024. Block 128x128x16, 256 threads = 8 warps,
// warp tile 64x32 via mma.sync.m16n8k8.tf32.
// Smem layout [k][m] / [k][n], stride 136 floats:
//   frag LDS:  addr%32 = col*8 + row  (col=lane&3, row=lane>>2) -> conflict-free
//   STS:       loader lr=tid&63 spans 32 consecutive m within a warp -> c-free
// mode 0: scatter output to [B,H,S,Dh]; mode 1: row-major [M,N].
// ---------------------------------------------------------------------------
#define GSTRIDE 136

__device__ __forceinline__ uint32_t f2tf32(float x) {
    uint32_t r;
    asm("cvt.rna.tf32.f32 %0, %1;" : "=r"(r) : "f"(x));
    return r;
}

__device__ __forceinline__ void mma_tf32(float* c, const uint32_t* a, const uint32_t* b) {
    asm volatile(
        "mma.sync.aligned.m16n8k8.row.col.f32.tf32.tf32.f32 "
        "{%0,%1,%2,%3}, {%4,%5,%6,%7}, {%8,%9}, {%0,%1,%2,%3};"
        : "+f"(c[0]), "+f"(c[1]), "+f"(c[2]), "+f"(c[3])
        : "r"(a[0]), "r"(a[1]), "r"(a[2]), "r"(a[3]), "r"(b[0]), "r"(b[1]));
}

__global__ __launch_bounds__(256) void gemm_tf32_kernel(
    const float* __restrict__ A, const float* __restrict__ B,
    float* __restrict__ C, int mode)
{
    __shared__ uint32_t As[16][GSTRIDE];
    __shared__ uint32_t Bs[16][GSTRIDE];

    const int tid  = threadIdx.x;
    const int warp = tid >> 5;
    const int lane = tid & 31;
    const int wm = warp >> 2;          // 0..1 -> m offset wm*64
    const int wn = warp & 3;           // 0..3 -> n offset wn*32
    const int row = lane >> 2;         // 0..7
    const int col = lane & 3;          // 0..3

    const int bm = blockIdx.y << 7;
    const int bn = blockIdx.x << 7;

    // loader: 32 consecutive rows per warp, one k-quad per thread-quarter
    const int lr = tid & 63;
    const int lc = (tid >> 6) << 2;    // 0,4,8,12

    const float* Ab = A + (bm + lr) * DMODEL + lc;
    const float* Bb = B + (bn + lr) * DMODEL + lc;

    float acc[4][4][4];
#pragma unroll
    for (int i = 0; i < 4; i++)
#pragma unroll
        for (int j = 0; j < 4; j++)
#pragma unroll
            for (int r = 0; r < 4; r++) acc[i][j][r] = 0.0f;

    for (int k0 = 0; k0 < DMODEL; k0 += 16) {
        float4 a0 = *(const float4*)(Ab + k0);
        float4 a1 = *(const float4*)(Ab + 64 * DMODEL + k0);
        float4 b0 = *(const float4*)(Bb + k0);
        float4 b1 = *(const float4*)(Bb + 64 * DMODEL + k0);
        __syncthreads();
        As[lc + 0][lr] = f2tf32(a0.x); As[lc + 1][lr] = f2tf32(a0.y);
        As[lc + 2][lr] = f2tf32(a0.z); As[lc + 3][lr] = f2tf32(a0.w);
        As[lc + 0][lr + 64] = f2tf32(a1.x); As[lc + 1][lr + 64] = f2tf32(a1.y);
        As[lc + 2][lr + 64] = f2tf32(a1.z); As[lc + 3][lr + 64] = f2tf32(a1.w);
        Bs[lc + 0][lr] = f2tf32(b0.x); Bs[lc + 1][lr] = f2tf32(b0.y);
        Bs[lc + 2][lr] = f2tf32(b0.z); Bs[lc + 3][lr] = f2tf32(b0.w);
        Bs[lc + 0][lr + 64] = f2tf32(b1.x); Bs[lc + 1][lr + 64] = f2tf32(b1.y);
        Bs[lc + 2][lr + 64] = f2tf32(b1.z); Bs[lc + 3][lr + 64] = f2tf32(b1.w);
        __syncthreads();

#pragma unroll
        for (int ks = 0; ks < 16; ks += 8) {
            uint32_t af[4][4], bf[4][2];
#pragma unroll
            for (int mt = 0; mt < 4; mt++) {
                const int m = wm * 64 + mt * 16 + row;
                af[mt][0] = As[ks + col][m];
                af[mt][1] = As[ks + col][m + 8];
                af[mt][2] = As[ks + col + 4][m];
                af[mt][3] = As[ks + col + 4][m + 8];
            }
#pragma unroll
            for (int nt = 0; nt < 4; nt++) {
                const int n = wn * 32 + nt * 8 + row;
                bf[nt][0] = Bs[ks + col][n];
                bf[nt][1] = Bs[ks + col + 4][n];
            }
#pragma unroll
            for (int mt = 0; mt < 4; mt++)
#pragma unroll
                for (int nt = 0; nt < 4; nt++)
                    mma_tf32(acc[mt][nt], af[mt], bf[nt]);
        }
    }

    // epilogue
#pragma unroll
    for (int mt = 0; mt < 4; mt++) {
        const int m0 = bm + wm * 64 + mt * 16 + row;
#pragma unroll
        for (int nt = 0; nt < 4; nt++) {
            const int n = bn + wn * 32 + nt * 8 + col * 2;
#pragma unroll
            for (int half = 0; half < 2; half++) {
                const int m = m0 + half * 8;
                float2 v = make_float2(acc[mt][nt][half * 2],
                                       acc[mt][nt][half * 2 + 1]);
                if (mode == 0) {
                    const int b = m >> 11;
                    const int s = m & (SEQ - 1);
                    const int h = n >> 6;
                    const int dh = n & 63;
                    *(float2*)&C[((b * NHEADS + h) * SEQ + s) * HDIM + dh] = v;
                } else {
                    *(float2*)&C[m * DMODEL + n] = v;
                }
            }
        }
    }
}

// ---------------------------------------------------------------------------
// Flash attention (fp32, causal) — unchanged from R1.
// ---------------------------------------------------------------------------
#define QS_STRIDE 68
#define KS_STRIDE 68
#define PS_STRIDE 65
#define ATT_SMEM_FLOATS (64 * QS_STRIDE + 64 * KS_STRIDE + 64 * 64 + 64 * PS_STRIDE)

__global__ __launch_bounds__(256) void attn_kernel(
    const float* __restrict__ Q, const float* __restrict__ K,
    const float* __restrict__ V, float* __restrict__ O)
{
    extern __shared__ float sm[];
    float* Qs = sm;                       // [64][68]
    float* Ks = Qs + 64 * QS_STRIDE;      // [64][68]
    float* Vs = Ks + 64 * KS_STRIDE;      // [64][64]
    float* Ps = Vs + 64 * 64;             // [64][65]

    const int tid = threadIdx.x;
    const int bh = blockIdx.y;            // b*16 + h
    const int q0 = blockIdx.x << 6;
    const float* Qb = Q + bh * (SEQ * HDIM);
    const float* Kb = K + bh * (SEQ * HDIM);
    const float* Vb = V + bh * (SEQ * HDIM);

    const int lr = tid >> 2;              // 0..63
    const int sub = tid & 3;
    const int lc = sub << 4;              // 0,16,32,48

#pragma unroll
    for (int c = 0; c < 16; c += 4)
        *(float4*)&Qs[lr * QS_STRIDE + lc + c] =
            *(const float4*)&Qb[(q0 + lr) * HDIM + lc + c];

    const int q = lr;
    float acc[16];
#pragma unroll
    for (int i = 0; i < 16; i++) acc[i] = 0.0f;
    float m_run = -1e30f, l_run = 0.0f;

    const int ntiles = blockIdx.x + 1;    // causal: k-tiles 0..qtile
    for (int t = 0; t < ntiles; t++) {
        const int k0 = t << 6;
        __syncthreads();
#pragma unroll
        for (int c = 0; c < 16; c += 4) {
            *(float4*)&Ks[lr * KS_STRIDE + lc + c] =
                *(const float4*)&Kb[(k0 + lr) * HDIM + lc + c];
            *(float4*)&Vs[lr * 64 + lc + c] =
                *(const float4*)&Vb[(k0 + lr) * HDIM + lc + c];
        }
        __syncthreads();

        float sc[16];
#pragma unroll
        for (int jj = 0; jj < 16; jj += 2) {
            const int ka = sub + 4 * jj;
            const int kb = ka + 4;
            float sa = 0.0f, sb = 0.0f;
#pragma unroll
            for (int d = 0; d < HDIM; d += 4) {
                float4 qv  = *(const float4*)&Qs[q * QS_STRIDE + d];
                float4 kva = *(const float4*)&Ks[ka * KS_STRIDE + d];
                float4 kvb = *(const float4*)&Ks[kb * KS_STRIDE + d];
                sa += qv.x * kva.x + qv.y * kva.y + qv.z * kva.z + qv.w * kva.w;
                sb += qv.x * kvb.x + qv.y * kvb.y + qv.z * kvb.z + qv.w * kvb.w;
            }
            sc[jj] = sa; sc[jj + 1] = sb;
        }

        const int qg = q0 + q;
#pragma unroll
        for (int jj = 0; jj < 16; jj++) {
            const int kg = k0 + sub + 4 * jj;
            sc[jj] = (kg <= qg) ? sc[jj] * 0.125f : -1e30f;
        }

        float tm = sc[0];
#pragma unroll
        for (int jj = 1; jj < 16; jj++) tm = fmaxf(tm, sc[jj]);
        tm = fmaxf(tm, __shfl_xor_sync(0xffffffffu, tm, 1));
        tm = fmaxf(tm, __shfl_xor_sync(0xffffffffu, tm, 2));
        const float m_new = fmaxf(m_run, tm);
        const float alpha = __expf(m_run - m_new);
        float lsum = 0.0f;
#pragma unroll
        for (int jj = 0; jj < 16; jj++) {
            const float p = __expf(sc[jj] - m_new);
            lsum += p;
            Ps[q * PS_STRIDE + sub + 4 * jj] = p;
        }
        lsum += __shfl_xor_sync(0xffffffffu, lsum, 1);
        lsum += __shfl_xor_sync(0xffffffffu, lsum, 2);
        l_run = l_run * alpha + lsum;
        m_run = m_new;
#pragma unroll
        for (int i = 0; i < 16; i++) acc[i] *= alpha;
        __syncthreads();

#pragma unroll 8
        for (int k = 0; k < 64; k++) {
            const float pk = Ps[q * PS_STRIDE + k];
#pragma unroll
            for (int j4 = 0; j4 < 4; j4++) {
                float4 vv = *(const float4*)&Vs[k * 64 + (sub << 2) + (j4 << 4)];
                acc[j4 * 4 + 0] += pk * vv.x;
                acc[j4 * 4 + 1] += pk * vv.y;
                acc[j4 * 4 + 2] += pk * vv.z;
                acc[j4 * 4 + 3] += pk * vv.w;
            }
        }
    }

    const float rinv = 1.0f / l_run;
    const int b = bh >> 4, h = bh & 15;
    float* Ob = O + (b * SEQ + q0 + q) * DMODEL + h * HDIM;
#pragma unroll
    for (int j4 = 0; j4 < 4; j4++) {
        float4 v = make_float4(acc[j4 * 4 + 0] * rinv, acc[j4 * 4 + 1] * rinv,
                               acc[j4 * 4 + 2] * rinv, acc[j4 * 4 + 3] * rinv);
        *(float4*)&Ob[(sub << 2) + (j4 << 4)] = v;
    }
}

// ---------------------------------------------------------------------------
extern "C" void kernel_launch(void* const* d_in, const int* in_sizes, int n_in,
                              void* d_out, int out_size)
{
    const float* x  = (const float*)d_in[0];
    const float* wq = (const float*)d_in[1];
    const float* wk = (const float*)d_in[2];
    const float* wv = (const float*)d_in[3];
    const float* wo = (const float*)d_in[4];
    float* out = (float*)d_out;

    float *pq, *pk, *pv, *pao;
    cudaGetSymbolAddress((void**)&pq,  g_q);
    cudaGetSymbolAddress((void**)&pk,  g_k);
    cudaGetSymbolAddress((void**)&pv,  g_v);
    cudaGetSymbolAddress((void**)&pao, g_ao);

    const dim3 ggrid(DMODEL / 128, MROWS / 128);   // (8, 64)
    gemm_tf32_kernel<<<ggrid, 256>>>(x, wq, pq, 0);
    gemm_tf32_kernel<<<ggrid, 256>>>(x, wk, pk, 0);
    gemm_tf32_kernel<<<ggrid, 256>>>(x, wv, pv, 0);

    cudaFuncSetAttribute(attn_kernel, cudaFuncAttributeMaxDynamicSharedMemorySize,
                         ATT_SMEM_FLOATS * (int)sizeof(float));
    const dim3 agrid(SEQ / 64, BATCH * NHEADS);    // (32, 64)
    attn_kernel<<<agrid, 256, ATT_SMEM_FLOATS * sizeof(float)>>>(pq, pk, pv, pao);

    gemm_tf32_kernel<<<ggrid, 256>>>(pao, wo, out, 1);
}

// round 3
// speedup vs baseline: 2.4193x; 2.0594x over previous
#include <cuda_runtime.h>
#include <cuda_bf16.h>
#include <cstdint>

// Shapes (fixed by the problem)
#define BATCH 4
#define SEQ 2048
#define DMODEL 1024
#define NHEADS 16
#define HDIM 64
#define MROWS (BATCH * SEQ)      // 8192

// Scratch (device globals: allocation is forbidden)
__device__ float g_q[BATCH * NHEADS * SEQ * HDIM];    // [B,H,S,Dh]
__device__ float g_k[BATCH * NHEADS * SEQ * HDIM];
__device__ float g_v[BATCH * NHEADS * SEQ * HDIM];
__device__ float g_ao[BATCH * SEQ * DMODEL];          // [B,S,D]

__device__ __forceinline__ uint32_t f2tf32(float x) {
    uint32_t r;
    asm("cvt.rna.tf32.f32 %0, %1;" : "=r"(r) : "f"(x));
    return r;
}

__device__ __forceinline__ void mma_tf32(float* c, const uint32_t* a, const uint32_t* b) {
    asm volatile(
        "mma.sync.aligned.m16n8k8.row.col.f32.tf32.tf32.f32 "
        "{%0,%1,%2,%3}, {%4,%5,%6,%7}, {%8,%9}, {%0,%1,%2,%3};"
        : "+f"(c[0]), "+f"(c[1]), "+f"(c[2]), "+f"(c[3])
        : "r"(a[0]), "r"(a[1]), "r"(a[2]), "r"(a[3]), "r"(b[0]), "r"(b[1]));
}

// ---------------------------------------------------------------------------
// tf32 tensor-core GEMM: C = A[M,K] * B[N,K]^T  (unchanged from R2)
// ---------------------------------------------------------------------------
#define GSTRIDE 136

__global__ __launch_bounds__(256) void gemm_tf32_kernel(
    const float* __restrict__ A, const float* __restrict__ B,
    float* __restrict__ C, int mode)
{
    __shared__ uint32_t As[16][GSTRIDE];
    __shared__ uint32_t Bs[16][GSTRIDE];

    const int tid  = threadIdx.x;
    const int warp = tid >> 5;
    const int lane = tid & 31;
    const int wm = warp >> 2;
    const int wn = warp & 3;
    const int row = lane >> 2;
    const int col = lane & 3;

    const int bm = blockIdx.y << 7;
    const int bn = blockIdx.x << 7;

    const int lr = tid & 63;
    const int lc = (tid >> 6) << 2;

    const float* Ab = A + (bm + lr) * DMODEL + lc;
    const float* Bb = B + (bn + lr) * DMODEL + lc;

    float acc[4][4][4];
#pragma unroll
    for (int i = 0; i < 4; i++)
#pragma unroll
        for (int j = 0; j < 4; j++)
#pragma unroll
            for (int r2 = 0; r2 < 4; r2++) acc[i][j][r2] = 0.0f;

    for (int k0 = 0; k0 < DMODEL; k0 += 16) {
        float4 a0 = *(const float4*)(Ab + k0);
        float4 a1 = *(const float4*)(Ab + 64 * DMODEL + k0);
        float4 b0 = *(const float4*)(Bb + k0);
        float4 b1 = *(const float4*)(Bb + 64 * DMODEL + k0);
        __syncthreads();
        As[lc + 0][lr] = f2tf32(a0.x); As[lc + 1][lr] = f2tf32(a0.y);
        As[lc + 2][lr] = f2tf32(a0.z); As[lc + 3][lr] = f2tf32(a0.w);
        As[lc + 0][lr + 64] = f2tf32(a1.x); As[lc + 1][lr + 64] = f2tf32(a1.y);
        As[lc + 2][lr + 64] = f2tf32(a1.z); As[lc + 3][lr + 64] = f2tf32(a1.w);
        Bs[lc + 0][lr] = f2tf32(b0.x); Bs[lc + 1][lr] = f2tf32(b0.y);
        Bs[lc + 2][lr] = f2tf32(b0.z); Bs[lc + 3][lr] = f2tf32(b0.w);
        Bs[lc + 0][lr + 64] = f2tf32(b1.x); Bs[lc + 1][lr + 64] = f2tf32(b1.y);
        Bs[lc + 2][lr + 64] = f2tf32(b1.z); Bs[lc + 3][lr + 64] = f2tf32(b1.w);
        __syncthreads();

#pragma unroll
        for (int ks = 0; ks < 16; ks += 8) {
            uint32_t af[4][4], bf[4][2];
#pragma unroll
            for (int mt = 0; mt < 4; mt++) {
                const int m = wm * 64 + mt * 16 + row;
                af[mt][0] = As[ks + col][m];
                af[mt][1] = As[ks + col][m + 8];
                af[mt][2] = As[ks + col + 4][m];
                af[mt][3] = As[ks + col + 4][m + 8];
            }
#pragma unroll
            for (int nt = 0; nt < 4; nt++) {
                const int n = wn * 32 + nt * 8 + row;
                bf[nt][0] = Bs[ks + col][n];
                bf[nt][1] = Bs[ks + col + 4][n];
            }
#pragma unroll
            for (int mt = 0; mt < 4; mt++)
#pragma unroll
                for (int nt = 0; nt < 4; nt++)
                    mma_tf32(acc[mt][nt], af[mt], bf[nt]);
        }
    }

#pragma unroll
    for (int mt = 0; mt < 4; mt++) {
        const int m0 = bm + wm * 64 + mt * 16 + row;
#pragma unroll
        for (int nt = 0; nt < 4; nt++) {
            const int n = bn + wn * 32 + nt * 8 + col * 2;
#pragma unroll
            for (int half = 0; half < 2; half++) {
                const int m = m0 + half * 8;
                float2 v = make_float2(acc[mt][nt][half * 2],
                                       acc[mt][nt][half * 2 + 1]);
                if (mode == 0) {
                    const int b = m >> 11;
                    const int s = m & (SEQ - 1);
                    const int h = n >> 6;
                    const int dh = n & 63;
                    *(float2*)&C[((b * NHEADS + h) * SEQ + s) * HDIM + dh] = v;
                } else {
                    *(float2*)&C[m * DMODEL + n] = v;
                }
            }
        }
    }
}

// ---------------------------------------------------------------------------
// Tensor-core flash attention (tf32 mma, causal).
// 128 threads = 4 warps; warp handles 16 q-rows of a 64-query tile.
// Q frags (pre-scaled by 1/8, tf32) resident in regs across the KV loop.
// Smem: Ks[64][68], Vs[64][72], Ps[64][68] (P as tf32 bits; also Q staging).
// All mma fragment LDS patterns are bank-conflict-free by stride choice.
// ---------------------------------------------------------------------------
#define AKS 68
#define AVS 72
#define APS 68
#define ATT_SMEM_FLOATS (64 * AKS + 64 * AVS + 64 * APS)

__global__ __launch_bounds__(128) void attn_mma_kernel(
    const float* __restrict__ Q, const float* __restrict__ K,
    const float* __restrict__ V, float* __restrict__ O)
{
    extern __shared__ float sm[];
    float* Ks = sm;                  // [64][68]
    float* Vs = Ks + 64 * AKS;       // [64][72]
    float* Ps = Vs + 64 * AVS;       // [64][68]
    uint32_t* Pu = (uint32_t*)Ps;

    const int tid  = threadIdx.x;
    const int warp = tid >> 5;
    const int lane = tid & 31;
    const int r = lane >> 2;         // 0..7
    const int c = lane & 3;          // 0..3

    const int bh = blockIdx.y;
    const int qt = gridDim.x - 1 - blockIdx.x;   // longest blocks first
    const int q0 = qt << 6;
    const float* Qb = Q + bh * (SEQ * HDIM);
    const float* Kb = K + bh * (SEQ * HDIM);
    const float* Vb = V + bh * (SEQ * HDIM);

    // loaders: 2 threads per row, 32 floats each
    const int lr  = tid >> 1;
    const int lc0 = (tid & 1) << 5;

    // ---- stage Q tile (into Ps), then build resident Q fragments ----
#pragma unroll
    for (int cc = 0; cc < 32; cc += 4)
        *(float4*)&Ps[lr * APS + lc0 + cc] =
            *(const float4*)&Qb[(q0 + lr) * HDIM + lc0 + cc];
    __syncthreads();

    const int qr = warp * 16 + r;
    uint32_t qf[8][4];
#pragma unroll
    for (int ks = 0; ks < 8; ks++) {
        const int d = ks * 8 + c;
        qf[ks][0] = f2tf32(0.125f * Ps[qr * APS + d]);
        qf[ks][1] = f2tf32(0.125f * Ps[(qr + 8) * APS + d]);
        qf[ks][2] = f2tf32(0.125f * Ps[qr * APS + d + 4]);
        qf[ks][3] = f2tf32(0.125f * Ps[(qr + 8) * APS + d + 4]);
    }

    float oacc[8][4];
#pragma unroll
    for (int nt = 0; nt < 8; nt++)
#pragma unroll
        for (int j = 0; j < 4; j++) oacc[nt][j] = 0.0f;
    float mrun[2] = {-1e30f, -1e30f};
    float lrun[2] = {0.0f, 0.0f};

    for (int t = 0; t <= qt; t++) {
        const int k0 = t << 6;
        __syncthreads();   // prev iter done with Ks/Vs (Ps Q-staging done too)
#pragma unroll
        for (int cc = 0; cc < 32; cc += 4) {
            *(float4*)&Ks[lr * AKS + lc0 + cc] =
                *(const float4*)&Kb[(k0 + lr) * HDIM + lc0 + cc];
            *(float4*)&Vs[lr * AVS + lc0 + cc] =
                *(const float4*)&Vb[(k0 + lr) * HDIM + lc0 + cc];
        }
        __syncthreads();

        // ---- scores: S = Q K^T (pre-scaled) ----
        float sacc[8][4];
#pragma unroll
        for (int nt = 0; nt < 8; nt++)
#pragma unroll
            for (int j = 0; j < 4; j++) sacc[nt][j] = 0.0f;

#pragma unroll
        for (int ks = 0; ks < 8; ks++) {
#pragma unroll
            for (int nt = 0; nt < 8; nt++) {
                uint32_t kb[2];
                const int base = (nt * 8 + r) * AKS + ks * 8 + c;
                kb[0] = f2tf32(Ks[base]);
                kb[1] = f2tf32(Ks[base + 4]);
                mma_tf32(sacc[nt], qf[ks], kb);
            }
        }

        // ---- causal mask (diagonal tile only; k0 == q0 there) ----
        if (t == qt) {
#pragma unroll
            for (int nt = 0; nt < 8; nt++) {
#pragma unroll
                for (int j = 0; j < 4; j++) {
                    const int kg = nt * 8 + 2 * c + (j & 1);
                    const int qg = warp * 16 + r + (j >> 1) * 8;
                    if (kg > qg) sacc[nt][j] = -1e30f;
                }
            }
        }

        // ---- online softmax (per row-half) ----
#pragma unroll
        for (int hh = 0; hh < 2; hh++) {
            float tm = -1e30f;
#pragma unroll
            for (int nt = 0; nt < 8; nt++)
                tm = fmaxf(tm, fmaxf(sacc[nt][2 * hh], sacc[nt][2 * hh + 1]));
            tm = fmaxf(tm, __shfl_xor_sync(0xffffffffu, tm, 1));
            tm = fmaxf(tm, __shfl_xor_sync(0xffffffffu, tm, 2));
            const float mnew  = fmaxf(mrun[hh], tm);
            const float alpha = __expf(mrun[hh] - mnew);
            float ls = 0.0f;
            const int prow = (warp * 16 + r + hh * 8) * APS;
#pragma unroll
            for (int nt = 0; nt < 8; nt++) {
                const float p0 = __expf(sacc[nt][2 * hh] - mnew);
                const float p1 = __expf(sacc[nt][2 * hh + 1] - mnew);
                ls += p0 + p1;
                uint2 pv = make_uint2(f2tf32(p0), f2tf32(p1));
                *(uint2*)&Pu[prow + nt * 8 + 2 * c] = pv;
            }
            ls += __shfl_xor_sync(0xffffffffu, ls, 1);
            ls += __shfl_xor_sync(0xffffffffu, ls, 2);
            lrun[hh] = lrun[hh] * alpha + ls;
            mrun[hh] = mnew;
#pragma unroll
            for (int nt = 0; nt < 8; nt++) {
                oacc[nt][2 * hh]     *= alpha;
                oacc[nt][2 * hh + 1] *= alpha;
            }
        }
        __syncwarp();   // P is warp-local in smem: order STS before LDS

        // ---- O += P V ----
#pragma unroll
        for (int ks = 0; ks < 8; ks++) {
            uint32_t pf[4];
            const int d = ks * 8 + c;
            pf[0] = Pu[qr * APS + d];
            pf[1] = Pu[(qr + 8) * APS + d];
            pf[2] = Pu[qr * APS + d + 4];
            pf[3] = Pu[(qr + 8) * APS + d + 4];
#pragma unroll
            for (int nt = 0; nt < 8; nt++) {
                uint32_t vb[2];
                vb[0] = f2tf32(Vs[(ks * 8 + c) * AVS + nt * 8 + r]);
                vb[1] = f2tf32(Vs[(ks * 8 + c + 4) * AVS + nt * 8 + r]);
                mma_tf32(oacc[nt], pf, vb);
            }
        }
    }

    // ---- epilogue: normalize and scatter to [B,S,D] ----
    const float rinv0 = 1.0f / lrun[0];
    const float rinv1 = 1.0f / lrun[1];
    const int b = bh >> 4, h = bh & 15;
    const int row0 = q0 + qr;
#pragma unroll
    for (int nt = 0; nt < 8; nt++) {
        const int dh = nt * 8 + 2 * c;
        float2 v0 = make_float2(oacc[nt][0] * rinv0, oacc[nt][1] * rinv0);
        float2 v1 = make_float2(oacc[nt][2] * rinv1, oacc[nt][3] * rinv1);
        *(float2*)&O[(b * SEQ + row0) * DMODEL + h * HDIM + dh] = v0;
        *(float2*)&O[(b * SEQ + row0 + 8) * DMODEL + h * HDIM + dh] = v1;
    }
}

// ---------------------------------------------------------------------------
extern "C" void kernel_launch(void* const* d_in, const int* in_sizes, int n_in,
                              void* d_out, int out_size)
{
    const float* x  = (const float*)d_in[0];
    const float* wq = (const float*)d_in[1];
    const float* wk = (const float*)d_in[2];
    const float* wv = (const float*)d_in[3];
    const float* wo = (const float*)d_in[4];
    float* out = (float*)d_out;

    float *pq, *pk, *pv, *pao;
    cudaGetSymbolAddress((void**)&pq,  g_q);
    cudaGetSymbolAddress((void**)&pk,  g_k);
    cudaGetSymbolAddress((void**)&pv,  g_v);
    cudaGetSymbolAddress((void**)&pao, g_ao);

    const dim3 ggrid(DMODEL / 128, MROWS / 128);   // (8, 64)
    gemm_tf32_kernel<<<ggrid, 256>>>(x, wq, pq, 0);
    gemm_tf32_kernel<<<ggrid, 256>>>(x, wk, pk, 0);
    gemm_tf32_kernel<<<ggrid, 256>>>(x, wv, pv, 0);

    cudaFuncSetAttribute(attn_mma_kernel, cudaFuncAttributeMaxDynamicSharedMemorySize,
                         ATT_SMEM_FLOATS * (int)sizeof(float));
    const dim3 agrid(SEQ / 64, BATCH * NHEADS);    // (32, 64)
    attn_mma_kernel<<<agrid, 128, ATT_SMEM_FLOATS * sizeof(float)>>>(pq, pk, pv, pao);

    gemm_tf32_kernel<<<ggrid, 256>>>(pao, wo, out, 1);
}

// round 4
// speedup vs baseline: 4.2636x; 1.7624x over previous
#include <cuda_runtime.h>
#include <cuda_bf16.h>
#include <cstdint>

#define BATCH 4
#define SEQ 2048
#define DMODEL 1024
#define NHEADS 16
#define HDIM 64
#define MROWS (BATCH * SEQ)      // 8192

__device__ float g_q[BATCH * NHEADS * SEQ * HDIM];    // [B,H,S,Dh]
__device__ float g_k[BATCH * NHEADS * SEQ * HDIM];
__device__ float g_v[BATCH * NHEADS * SEQ * HDIM];
__device__ float g_ao[BATCH * SEQ * DMODEL];          // [B,S,D]

__device__ __forceinline__ uint32_t f2tf32(float x) {
    uint32_t r;
    asm("cvt.rna.tf32.f32 %0, %1;" : "=r"(r) : "f"(x));
    return r;
}
__device__ __forceinline__ void mma_tf32(float* c, const uint32_t* a, const uint32_t* b) {
    asm volatile(
        "mma.sync.aligned.m16n8k8.row.col.f32.tf32.tf32.f32 "
        "{%0,%1,%2,%3}, {%4,%5,%6,%7}, {%8,%9}, {%0,%1,%2,%3};"
        : "+f"(c[0]), "+f"(c[1]), "+f"(c[2]), "+f"(c[3])
        : "r"(a[0]), "r"(a[1]), "r"(a[2]), "r"(a[3]), "r"(b[0]), "r"(b[1]));
}
__device__ __forceinline__ uint32_t smem_u32(const void* p) {
    return (uint32_t)__cvta_generic_to_shared(p);
}
__device__ __forceinline__ void cp16(uint32_t dst, const void* src) {
    asm volatile("cp.async.cg.shared.global [%0], [%1], 16;" :: "r"(dst), "l"(src));
}
__device__ __forceinline__ void cp_commit() { asm volatile("cp.async.commit_group;"); }
template<int N> __device__ __forceinline__ void cp_wait() {
    asm volatile("cp.async.wait_group %0;" :: "n"(N));
}

// ---------------------------------------------------------------------------
// Pipelined tf32 GEMM: C = A[M,K] * B[N,K]^T. 128x128 block, BK=16, 4-stage
// cp.async. Smem row-major [m][k] stride 20 (frag LDS banks 4r+c: c-free).
// mode 0: scatter to [B,H,S,Dh]; mode 1: row-major [M,N].
// ---------------------------------------------------------------------------
#define GKS 20
#define GEMM_SMEM_FLOATS (2 * 4 * 128 * GKS)

__global__ __launch_bounds__(256, 2) void gemm_tf32_pipe(
    const float* __restrict__ A, const float* __restrict__ Bw,
    float* __restrict__ C, int mode)
{
    extern __shared__ float gsm[];
    float* As = gsm;                    // [4][128][20]
    float* Bs = gsm + 4 * 128 * GKS;    // [4][128][20]

    const int tid  = threadIdx.x;
    const int warp = tid >> 5;
    const int lane = tid & 31;
    const int wm = warp >> 2;           // 0..1
    const int wn = warp & 3;            // 0..3
    const int r = lane >> 2;            // 0..7
    const int c = lane & 3;             // 0..3

    const int bm = blockIdx.y << 7;
    const int bn = blockIdx.x << 7;

    // loader: 4 lanes per row (16B chunks), rows lrw and lrw+64
    const int lch = tid & 3;
    const int lrw = tid >> 2;           // 0..63
    const float* Agl = A  + (bm + lrw) * DMODEL + lch * 4;
    const float* Bgl = Bw + (bn + lrw) * DMODEL + lch * 4;
    const uint32_t aB = smem_u32(As);
    const uint32_t bB = smem_u32(Bs);
    const uint32_t dOff = ((uint32_t)(lrw * GKS + lch * 4)) * 4u;
    const uint32_t rowHalf = 64u * GKS * 4u;

    auto issue = [&](int s) {
        const int buf = s & 3;
        const int k0 = s << 4;
        const uint32_t sb = (uint32_t)(buf * 128 * GKS) * 4u;
        cp16(aB + sb + dOff, Agl + k0);
        cp16(aB + sb + dOff + rowHalf, Agl + 64 * DMODEL + k0);
        cp16(bB + sb + dOff, Bgl + k0);
        cp16(bB + sb + dOff + rowHalf, Bgl + 64 * DMODEL + k0);
    };

    issue(0); cp_commit();
    issue(1); cp_commit();
    issue(2); cp_commit();

    float acc[4][4][4];
#pragma unroll
    for (int i = 0; i < 4; i++)
#pragma unroll
        for (int j = 0; j < 4; j++)
#pragma unroll
            for (int q = 0; q < 4; q++) acc[i][j][q] = 0.0f;

    for (int t = 0; t < 64; t++) {
        cp_wait<2>();
        __syncthreads();
        if (t + 3 < 64) issue(t + 3);
        cp_commit();

        const float* Ab = As + (t & 3) * 128 * GKS;
        const float* Bb = Bs + (t & 3) * 128 * GKS;
#pragma unroll
        for (int ks = 0; ks < 16; ks += 8) {
            uint32_t af[4][4], bf[4][2];
#pragma unroll
            for (int mt = 0; mt < 4; mt++) {
                const int m = wm * 64 + mt * 16 + r;
                af[mt][0] = f2tf32(Ab[m * GKS + ks + c]);
                af[mt][1] = f2tf32(Ab[(m + 8) * GKS + ks + c]);
                af[mt][2] = f2tf32(Ab[m * GKS + ks + c + 4]);
                af[mt][3] = f2tf32(Ab[(m + 8) * GKS + ks + c + 4]);
            }
#pragma unroll
            for (int nt = 0; nt < 4; nt++) {
                const int n = wn * 32 + nt * 8 + r;
                bf[nt][0] = f2tf32(Bb[n * GKS + ks + c]);
                bf[nt][1] = f2tf32(Bb[n * GKS + ks + c + 4]);
            }
#pragma unroll
            for (int mt = 0; mt < 4; mt++)
#pragma unroll
                for (int nt = 0; nt < 4; nt++)
                    mma_tf32(acc[mt][nt], af[mt], bf[nt]);
        }
    }

#pragma unroll
    for (int mt = 0; mt < 4; mt++) {
        const int m0 = bm + wm * 64 + mt * 16 + r;
#pragma unroll
        for (int nt = 0; nt < 4; nt++) {
            const int n = bn + wn * 32 + nt * 8 + c * 2;
#pragma unroll
            for (int half = 0; half < 2; half++) {
                const int m = m0 + half * 8;
                float2 v = make_float2(acc[mt][nt][half * 2],
                                       acc[mt][nt][half * 2 + 1]);
                if (mode == 0) {
                    const int b = m >> 11;
                    const int s = m & (SEQ - 1);
                    const int h = n >> 6;
                    const int dh = n & 63;
                    *(float2*)&C[((b * NHEADS + h) * SEQ + s) * HDIM + dh] = v;
                } else {
                    *(float2*)&C[m * DMODEL + n] = v;
                }
            }
        }
    }
}

// ---------------------------------------------------------------------------
// Pipelined tf32 flash attention (causal). 256 threads = 8 warps; q-tile 128
// (warp = 16 q-rows), kv-tile 64, double-buffered K/V via cp.async.
// ---------------------------------------------------------------------------
#define AKS 68
#define AVS 72
#define APS 68
#define ATT_SMEM_FLOATS (2 * 64 * AKS + 2 * 64 * AVS + 128 * APS)

__global__ __launch_bounds__(256, 2) void attn_pipe_kernel(
    const float* __restrict__ Q, const float* __restrict__ K,
    const float* __restrict__ V, float* __restrict__ O)
{
    extern __shared__ float smf[];
    float* Ks = smf;                         // [2][64][68]
    float* Vs = smf + 2 * 64 * AKS;          // [2][64][72]
    float* Ps = smf + 2 * 64 * AKS + 2 * 64 * AVS;  // [128][68]
    uint32_t* Pu = (uint32_t*)Ps;

    const int tid  = threadIdx.x;
    const int warp = tid >> 5;
    const int lane = tid & 31;
    const int r = lane >> 2;
    const int c = lane & 3;

    const int bh = blockIdx.y;
    const int QT = gridDim.x - 1 - blockIdx.x;    // longest first
    const int q0 = QT << 7;
    const float* Qb = Q + bh * (SEQ * HDIM);
    const float* Kb = K + bh * (SEQ * HDIM);
    const float* Vb = V + bh * (SEQ * HDIM);

    // ---- stage Q tile (128x64) into Ps ----
    {
        const int qrow = tid >> 1;
        const int qcol = (tid & 1) << 5;
#pragma unroll
        for (int cc = 0; cc < 32; cc += 4)
            *(float4*)&Ps[qrow * APS + qcol + cc] =
                *(const float4*)&Qb[(q0 + qrow) * HDIM + qcol + cc];
    }
    __syncthreads();

    const int qr = warp * 16 + r;
    uint32_t qf[8][4];
#pragma unroll
    for (int ks = 0; ks < 8; ks++) {
        const int d = ks * 8 + c;
        qf[ks][0] = f2tf32(0.125f * Ps[qr * APS + d]);
        qf[ks][1] = f2tf32(0.125f * Ps[(qr + 8) * APS + d]);
        qf[ks][2] = f2tf32(0.125f * Ps[qr * APS + d + 4]);
        qf[ks][3] = f2tf32(0.125f * Ps[(qr + 8) * APS + d + 4]);
    }

    // ---- KV loader (cp.async): 16 lanes cover a 256B row ----
    const int ch  = tid & 15;
    const int lr0 = tid >> 4;                // 0..15, rows lr0+16j
    const uint32_t ksB = smem_u32(Ks);
    const uint32_t vsB = smem_u32(Vs);

    auto issue_kv = [&](int t) {
        const int buf = t & 1;
        const int k0 = t << 6;
#pragma unroll
        for (int j = 0; j < 4; j++) {
            const int row = lr0 + 16 * j;
            cp16(ksB + ((buf * 64 + row) * AKS + ch * 4) * 4u,
                 Kb + (k0 + row) * HDIM + ch * 4);
            cp16(vsB + ((buf * 64 + row) * AVS + ch * 4) * 4u,
                 Vb + (k0 + row) * HDIM + ch * 4);
        }
    };

    issue_kv(0); cp_commit();

    float oacc[8][4];
#pragma unroll
    for (int nt = 0; nt < 8; nt++)
#pragma unroll
        for (int j = 0; j < 4; j++) oacc[nt][j] = 0.0f;
    float mrun[2] = {-1e30f, -1e30f};
    float lrun[2] = {0.0f, 0.0f};

    const int T = 2 * QT + 1;
    for (int t = 0; t <= T; t++) {
        cp_wait<0>();
        __syncthreads();          // data visible; prev compute done (bufs free)
        if (t < T) issue_kv(t + 1);
        cp_commit();

        const float* Kt = Ks + (t & 1) * 64 * AKS;
        const float* Vt = Vs + (t & 1) * 64 * AVS;

        // ---- scores ----
        float sacc[8][4];
#pragma unroll
        for (int nt = 0; nt < 8; nt++)
#pragma unroll
            for (int j = 0; j < 4; j++) sacc[nt][j] = 0.0f;
#pragma unroll
        for (int ks = 0; ks < 8; ks++) {
#pragma unroll
            for (int nt = 0; nt < 8; nt++) {
                uint32_t kb[2];
                const int base = (nt * 8 + r) * AKS + ks * 8 + c;
                kb[0] = f2tf32(Kt[base]);
                kb[1] = f2tf32(Kt[base + 4]);
                mma_tf32(sacc[nt], qf[ks], kb);
            }
        }

        // ---- causal mask (only near-diagonal tiles need it) ----
        if (t >= 2 * QT) {
            const int kbase = t << 6;
#pragma unroll
            for (int nt = 0; nt < 8; nt++)
#pragma unroll
                for (int j = 0; j < 4; j++) {
                    const int kg = kbase + nt * 8 + 2 * c + (j & 1);
                    const int qg = q0 + warp * 16 + r + (j >> 1) * 8;
                    if (kg > qg) sacc[nt][j] = -1e30f;
                }
        }

        // ---- online softmax ----
#pragma unroll
        for (int hh = 0; hh < 2; hh++) {
            float tm = -1e30f;
#pragma unroll
            for (int nt = 0; nt < 8; nt++)
                tm = fmaxf(tm, fmaxf(sacc[nt][2 * hh], sacc[nt][2 * hh + 1]));
            tm = fmaxf(tm, __shfl_xor_sync(0xffffffffu, tm, 1));
            tm = fmaxf(tm, __shfl_xor_sync(0xffffffffu, tm, 2));
            const float mnew  = fmaxf(mrun[hh], tm);
            const float alpha = __expf(mrun[hh] - mnew);
            float ls = 0.0f;
            const int prow = (warp * 16 + r + hh * 8) * APS;
#pragma unroll
            for (int nt = 0; nt < 8; nt++) {
                const float p0 = __expf(sacc[nt][2 * hh] - mnew);
                const float p1 = __expf(sacc[nt][2 * hh + 1] - mnew);
                ls += p0 + p1;
                uint2 pv = make_uint2(f2tf32(p0), f2tf32(p1));
                *(uint2*)&Pu[prow + nt * 8 + 2 * c] = pv;
            }
            ls += __shfl_xor_sync(0xffffffffu, ls, 1);
            ls += __shfl_xor_sync(0xffffffffu, ls, 2);
            lrun[hh] = lrun[hh] * alpha + ls;
            mrun[hh] = mnew;
#pragma unroll
            for (int nt = 0; nt < 8; nt++) {
                oacc[nt][2 * hh]     *= alpha;
                oacc[nt][2 * hh + 1] *= alpha;
            }
        }
        __syncwarp();   // P region is warp-local: order STS before LDS

        // ---- O += P V ----
#pragma unroll
        for (int ks = 0; ks < 8; ks++) {
            uint32_t pf[4];
            const int d = ks * 8 + c;
            pf[0] = Pu[qr * APS + d];
            pf[1] = Pu[(qr + 8) * APS + d];
            pf[2] = Pu[qr * APS + d + 4];
            pf[3] = Pu[(qr + 8) * APS + d + 4];
#pragma unroll
            for (int nt = 0; nt < 8; nt++) {
                uint32_t vb[2];
                vb[0] = f2tf32(Vt[(ks * 8 + c) * AVS + nt * 8 + r]);
                vb[1] = f2tf32(Vt[(ks * 8 + c + 4) * AVS + nt * 8 + r]);
                mma_tf32(oacc[nt], pf, vb);
            }
        }
    }

    // ---- epilogue ----
    const float rinv0 = 1.0f / lrun[0];
    const float rinv1 = 1.0f / lrun[1];
    const int b = bh >> 4, h = bh & 15;
    const int row0 = q0 + qr;
#pragma unroll
    for (int nt = 0; nt < 8; nt++) {
        const int dh = nt * 8 + 2 * c;
        float2 v0 = make_float2(oacc[nt][0] * rinv0, oacc[nt][1] * rinv0);
        float2 v1 = make_float2(oacc[nt][2] * rinv1, oacc[nt][3] * rinv1);
        *(float2*)&O[(b * SEQ + row0) * DMODEL + h * HDIM + dh] = v0;
        *(float2*)&O[(b * SEQ + row0 + 8) * DMODEL + h * HDIM + dh] = v1;
    }
}

// ---------------------------------------------------------------------------
extern "C" void kernel_launch(void* const* d_in, const int* in_sizes, int n_in,
                              void* d_out, int out_size)
{
    const float* x  = (const float*)d_in[0];
    const float* wq = (const float*)d_in[1];
    const float* wk = (const float*)d_in[2];
    const float* wv = (const float*)d_in[3];
    const float* wo = (const float*)d_in[4];
    float* out = (float*)d_out;

    float *pq, *pk, *pv, *pao;
    cudaGetSymbolAddress((void**)&pq,  g_q);
    cudaGetSymbolAddress((void**)&pk,  g_k);
    cudaGetSymbolAddress((void**)&pv,  g_v);
    cudaGetSymbolAddress((void**)&pao, g_ao);

    static int inited = 0;
    if (!inited) {
        cudaFuncSetAttribute(gemm_tf32_pipe, cudaFuncAttributeMaxDynamicSharedMemorySize,
                             GEMM_SMEM_FLOATS * (int)sizeof(float));
        cudaFuncSetAttribute(attn_pipe_kernel, cudaFuncAttributeMaxDynamicSharedMemorySize,
                             ATT_SMEM_FLOATS * (int)sizeof(float));
        inited = 1;
    }

    const dim3 ggrid(DMODEL / 128, MROWS / 128);   // (8, 64)
    const size_t gsm = GEMM_SMEM_FLOATS * sizeof(float);
    gemm_tf32_pipe<<<ggrid, 256, gsm>>>(x, wq, pq, 0);
    gemm_tf32_pipe<<<ggrid, 256, gsm>>>(x, wk, pk, 0);
    gemm_tf32_pipe<<<ggrid, 256, gsm>>>(x, wv, pv, 0);

    const dim3 agrid(SEQ / 128, BATCH * NHEADS);   // (16, 64)
    attn_pipe_kernel<<<agrid, 256, ATT_SMEM_FLOATS * sizeof(float)>>>(pq, pk, pv, pao);

    gemm_tf32_pipe<<<ggrid, 256, gsm>>>(pao, wo, out, 1);
}